// round 2
// baseline (speedup 1.0000x reference)
#include <cuda_runtime.h>

// RotatedNMSLayer: sigmoid -> threshold -> stable sort by conf desc -> greedy NMS
// (axis-aligned IoU > 0.25) -> emit [x1,y1,x2,y2,angle,conf,cls=0] at sorted
// positions, zeros elsewhere. NUM_CLASSES==1 so the class-offset trick in the
// reference is identically zero and obx == boxes.
//
// Single block, 1024 threads, everything resident in shared memory.

#define NMAX    5376
#define NPAD    8192        // next pow2 >= NMAX, bitonic size
#define THREADS 1024
#define IOU_THR 0.25f

extern __shared__ unsigned char smem_raw[];

__global__ __launch_bounds__(THREADS, 1)
void rotated_nms_kernel(const float* __restrict__ ps,   // pred_scores   (N,1)
                        const float* __restrict__ pb,   // pred_bboxes   (N,4)
                        const float* __restrict__ pa,   // pred_angles   (N,1)
                        const float* __restrict__ ap,   // anchor_points (N,2)
                        const float* __restrict__ st,   // stride_tensor (N,1)
                        const float* __restrict__ ct,   // conf_threshold(1,)
                        float* __restrict__ out,        // (N,7)
                        int N)
{
    // --- shared memory layout ---
    unsigned long long* keys = (unsigned long long*)smem_raw;        // 65536 B
    float* sx1 = (float*)(smem_raw + (size_t)NPAD * 8);
    float* sy1 = sx1 + NMAX;
    float* sx2 = sy1 + NMAX;
    float* sy2 = sx2 + NMAX;
    float* sar = sy2 + NMAX;
    unsigned char* alive = (unsigned char*)(sar + NMAX);             // NMAX B
    __shared__ int s_vcount;
    __shared__ int s_head;

    const int tid = threadIdx.x;
    if (tid == 0) s_vcount = 0;
    __syncthreads();

    const float thr = ct[0];

    // --- Phase A: build sort keys: (~ord(conf_m) << 32) | idx ---
    // Ascending u64 sort => conf descending, index ascending on ties
    // (matches JAX stable argsort of -conf_m). Invalid entries get conf_m=-1.
    int cnt = 0;
    for (int i = tid; i < NPAD; i += THREADS) {
        unsigned long long key = 0xFFFFFFFFFFFFFFFFULL;
        if (i < N) {
            float x    = ps[i];
            float conf = 1.0f / (1.0f + expf(-x));
            bool  valid = (conf >= thr);
            float cm   = valid ? conf : -1.0f;
            unsigned u = __float_as_uint(cm);
            u = (u & 0x80000000u) ? ~u : (u | 0x80000000u);  // total order
            u = ~u;                                          // descending
            key = ((unsigned long long)u << 32) | (unsigned)i;
            cnt += valid ? 1 : 0;
        }
        keys[i] = key;
    }
    atomicAdd(&s_vcount, cnt);

    // --- Phase B: bitonic sort (ascending) of NPAD u64 keys in SMEM ---
    for (int k = 2; k <= NPAD; k <<= 1) {
        for (int j = k >> 1; j > 0; j >>= 1) {
            __syncthreads();
            #pragma unroll
            for (int s = 0; s < NPAD / THREADS; s++) {
                int i   = tid + s * THREADS;
                int ixj = i ^ j;
                if (ixj > i) {
                    unsigned long long a = keys[i], b = keys[ixj];
                    bool up = ((i & k) == 0);
                    if ((a > b) == up) { keys[i] = b; keys[ixj] = a; }
                }
            }
        }
    }
    __syncthreads();
    const int V = s_vcount;   // valid entries occupy sorted positions [0, V)

    // --- Phase C: gather boxes in sorted order into SMEM ---
    for (int p = tid; p < N; p += THREADS) {
        float x1 = 0.f, y1 = 0.f, x2 = 0.f, y2 = 0.f;
        if (p < V) {
            int   idx = (int)(keys[p] & 0xFFFFFFFFu);
            float ax  = ap[idx * 2 + 0];
            float ay  = ap[idx * 2 + 1];
            float s   = st[idx];
            float l = pb[idx * 4 + 0], t = pb[idx * 4 + 1];
            float r = pb[idx * 4 + 2], b = pb[idx * 4 + 3];
            x1 = (ax - l) * s;  y1 = (ay - t) * s;
            x2 = (ax + r) * s;  y2 = (ay + b) * s;
            alive[p] = 1;
        } else {
            alive[p] = 0;
        }
        sx1[p] = x1; sy1[p] = y1; sx2[p] = x2; sy2[p] = y2;
        sar[p] = (x2 - x1) * (y2 - y1);
    }
    __syncthreads();

    // --- Phase D: greedy NMS ---
    // Thread 0 advances the head to the next surviving candidate (amortized
    // O(V) total); all threads suppress later candidates with IoU > thr.
    int h_prev = -1;
    while (true) {
        if (tid == 0) {
            int h = h_prev + 1;
            while (h < V && alive[h] == 0) h++;
            s_head = h;
        }
        __syncthreads();
        int h = s_head;
        if (h >= V) break;
        float hx1 = sx1[h], hy1 = sy1[h], hx2 = sx2[h], hy2 = sy2[h], ha = sar[h];
        for (int p = h + 1 + tid; p < V; p += THREADS) {
            if (alive[p]) {
                float iw = fminf(hx2, sx2[p]) - fmaxf(hx1, sx1[p]);
                float ih = fminf(hy2, sy2[p]) - fmaxf(hy1, sy1[p]);
                iw = fmaxf(iw, 0.0f);
                ih = fmaxf(ih, 0.0f);
                float inter = iw * ih;
                float iou   = inter / (ha + sar[p] - inter);  // NaN>thr == false, matches ref
                if (iou > IOU_THR) alive[p] = 0;
            }
        }
        h_prev = h;
        __syncthreads();
    }

    // --- Phase E: emit output (zeros where not kept; covers whole buffer) ---
    for (int p = tid; p < N; p += THREADS) {
        float o0 = 0.f, o1 = 0.f, o2 = 0.f, o3 = 0.f, o4 = 0.f, o5 = 0.f, o6 = 0.f;
        if (p < V && alive[p]) {
            unsigned long long key = keys[p];
            int idx = (int)(key & 0xFFFFFFFFu);
            // decode conf back from key (exact bit round-trip)
            unsigned f = ~(unsigned)(key >> 32);
            unsigned u = (f & 0x80000000u) ? (f ^ 0x80000000u) : ~f;
            float conf = __uint_as_float(u);
            o0 = sx1[p]; o1 = sy1[p]; o2 = sx2[p]; o3 = sy2[p];
            o4 = pa[idx];
            o5 = conf;
            o6 = 0.0f;   // cls == 0 always (NUM_CLASSES == 1)
        }
        float* o = out + (size_t)p * 7;
        o[0] = o0; o[1] = o1; o[2] = o2; o[3] = o3; o[4] = o4; o[5] = o5; o[6] = o6;
    }
}

extern "C" void kernel_launch(void* const* d_in, const int* in_sizes, int n_in,
                              void* d_out, int out_size)
{
    const float* ps = (const float*)d_in[0];   // pred_scores
    const float* pb = (const float*)d_in[1];   // pred_bboxes
    const float* pa = (const float*)d_in[2];   // pred_angles
    const float* ap = (const float*)d_in[3];   // anchor_points
    const float* st = (const float*)d_in[4];   // stride_tensor
    const float* ct = (const float*)d_in[5];   // conf_threshold

    int N = in_sizes[0];   // 5376

    // keys (NPAD*8) + 5 float arrays (NMAX*4 each) + alive flags (NMAX)
    const int smem_bytes = NPAD * 8 + NMAX * 4 * 5 + NMAX;   // 178432

    cudaFuncSetAttribute(rotated_nms_kernel,
                         cudaFuncAttributeMaxDynamicSharedMemorySize, smem_bytes);

    rotated_nms_kernel<<<1, THREADS, smem_bytes>>>(ps, pb, pa, ap, st, ct,
                                                   (float*)d_out, N);
}